// round 2
// baseline (speedup 1.0000x reference)
#include <cuda_runtime.h>

#define BB 2
#define SS 2048
#define DD 128
#define HH 8
#define EPSF 1e-10f

// Scratch (allocation-free rule: __device__ globals)
__device__ int g_tt[BB * SS];
__device__ int g_lo[BB * SS];
__device__ int g_hi[BB * SS];

// ---------------------------------------------------------------------------
// Kernel A: one warp per (b,s) row. logits = x . W^T + b, add gumbel, argmax.
// ---------------------------------------------------------------------------
__global__ void k_tt(const float* __restrict__ x,
                     const float* __restrict__ gu,
                     const float* __restrict__ W,
                     const float* __restrict__ bias) {
    int gwarp = (blockIdx.x * blockDim.x + threadIdx.x) >> 5;
    int lane  = threadIdx.x & 31;
    if (gwarp >= BB * SS) return;

    const float4* xr = reinterpret_cast<const float4*>(x + (size_t)gwarp * DD);
    float4 xv = xr[lane];  // 32 lanes * 4 = 128 elems, coalesced

    const float4* W4 = reinterpret_cast<const float4*>(W);
    float acc0, acc1, acc2;
    {
        float4 w0 = W4[0 * 32 + lane];
        float4 w1 = W4[1 * 32 + lane];
        float4 w2 = W4[2 * 32 + lane];
        acc0 = xv.x * w0.x + xv.y * w0.y + xv.z * w0.z + xv.w * w0.w;
        acc1 = xv.x * w1.x + xv.y * w1.y + xv.z * w1.z + xv.w * w1.w;
        acc2 = xv.x * w2.x + xv.y * w2.y + xv.z * w2.z + xv.w * w2.w;
    }
    #pragma unroll
    for (int off = 16; off; off >>= 1) {
        acc0 += __shfl_xor_sync(0xffffffffu, acc0, off);
        acc1 += __shfl_xor_sync(0xffffffffu, acc1, off);
        acc2 += __shfl_xor_sync(0xffffffffu, acc2, off);
    }

    if (lane == 0) {
        const float* gr = gu + (size_t)gwarp * 3;
        float g0 = -logf(-logf(gr[0] + EPSF) + EPSF);
        float g1 = -logf(-logf(gr[1] + EPSF) + EPSF);
        float g2 = -logf(-logf(gr[2] + EPSF) + EPSF);
        float s0 = acc0 + bias[0] + g0;
        float s1 = acc1 + bias[1] + g1;
        float s2 = acc2 + bias[2] + g2;
        int tt = 0; float best = s0;
        if (s1 > best) { best = s1; tt = 1; }   // strictly-greater = first-max wins
        if (s2 > best) { best = s2; tt = 2; }
        g_tt[gwarp] = tt;
    }
}

// ---------------------------------------------------------------------------
// Kernel B: per-batch suffix-min scan of gidx, emit per-row [lo, hi].
// ---------------------------------------------------------------------------
__global__ void k_scan() {
    int b   = blockIdx.x;
    int tid = threadIdx.x;  // 1024 threads
    __shared__ int sg[SS];
    __shared__ int tmp[SS];

    for (int s = tid; s < SS; s += 1024) {
        int tt = g_tt[b * SS + s];
        sg[s] = (tt == 0) ? s : SS;
    }
    __syncthreads();

    // Hillis-Steele reverse inclusive min scan
    for (int off = 1; off < SS; off <<= 1) {
        for (int s = tid; s < SS; s += 1024) {
            int other = (s + off < SS) ? sg[s + off] : SS;
            tmp[s] = min(sg[s], other);
        }
        __syncthreads();
        for (int s = tid; s < SS; s += 1024) sg[s] = tmp[s];
        __syncthreads();
    }

    for (int s = tid; s < SS; s += 1024) {
        int ng = (s + 1 < SS) ? sg[s + 1] : SS;   // next_global[s]
        int tt = g_tt[b * SS + s];
        int lo = 0, hi = s;
        if (tt == 1)      { lo = s; hi = s; }
        else if (tt == 2) { hi = min(s, ng); }
        g_lo[b * SS + s] = lo;
        g_hi[b * SS + s] = hi;
    }
}

// ---------------------------------------------------------------------------
// Kernel C: stream 268 MB of mask. One block per (b,h,s) row: 2048 floats.
// ---------------------------------------------------------------------------
__global__ void __launch_bounds__(256) k_write(float4* __restrict__ out) {
    int row = blockIdx.x;            // over B*H*S = 32768
    int s   = row & (SS - 1);
    int b   = row >> 14;             // / (H*S) = / 16384
    int lo  = g_lo[b * SS + s];
    int hi  = g_hi[b * SS + s];

    float4* orow = out + (size_t)row * (SS / 4);
    int tid = threadIdx.x;
    #pragma unroll
    for (int it = 0; it < (SS / 4) / 256; it++) {
        int q = it * 256 + tid;
        int j = q << 2;
        float4 v;
        v.x = (j     >= lo && j     <= hi) ? 1.0f : 0.0f;
        v.y = (j + 1 >= lo && j + 1 <= hi) ? 1.0f : 0.0f;
        v.z = (j + 2 >= lo && j + 2 <= hi) ? 1.0f : 0.0f;
        v.w = (j + 3 >= lo && j + 3 <= hi) ? 1.0f : 0.0f;
        orow[q] = v;
    }
}

extern "C" void kernel_launch(void* const* d_in, const int* in_sizes, int n_in,
                              void* d_out, int out_size) {
    const float* x    = (const float*)d_in[0];  // input_tensor (B,S,D)
    // d_in[1] = token_types (unused by reference)
    const float* gu   = (const float*)d_in[2];  // gumbel_u (B,S,3)
    const float* W    = (const float*)d_in[3];  // (3,D)
    const float* bias = (const float*)d_in[4];  // (3,)
    float4* out = (float4*)d_out;

    int nwarps = BB * SS;                        // 4096 rows
    k_tt<<<(nwarps * 32 + 255) / 256, 256>>>(x, gu, W, bias);
    k_scan<<<BB, 1024>>>();
    k_write<<<BB * HH * SS, 256>>>(out);
}

// round 3
// speedup vs baseline: 1.0020x; 1.0020x over previous
#include <cuda_runtime.h>

#define BB 2
#define SS 2048
#define DD 128
#define HH 8
#define EPSF 1e-10f
#define FULLM 0xffffffffu

// Scratch (allocation-free rule: __device__ globals)
__device__ int g_tt[BB * SS];
__device__ int g_lo[BB * SS];
__device__ int g_hi[BB * SS];

// ---------------------------------------------------------------------------
// Kernel A: 8 threads per (b,s) row. logits = x . W^T + b, + gumbel, argmax.
// 128 blocks x 256 threads; each thread: 4 independent float4 loads (MLP=4),
// 3-stage 8-lane shuffle reduce (9 shuffles vs 15 before).
// ---------------------------------------------------------------------------
__global__ void __launch_bounds__(256) k_tt(const float* __restrict__ x,
                                            const float* __restrict__ gu,
                                            const float* __restrict__ W,
                                            const float* __restrict__ bias) {
    int gid  = blockIdx.x * 256 + threadIdx.x;
    int row  = gid >> 3;          // (b*S + s), 4096 rows
    int r    = gid & 7;           // sub-lane within row group

    const float4* xr = reinterpret_cast<const float4*>(x + (size_t)row * DD);
    const float4* W4 = reinterpret_cast<const float4*>(W);

    float4 xv[4];
    #pragma unroll
    for (int i = 0; i < 4; i++) xv[i] = xr[r * 4 + i];   // 4 independent LDG.128

    float acc0 = 0.f, acc1 = 0.f, acc2 = 0.f;
    #pragma unroll
    for (int i = 0; i < 4; i++) {
        int c = r * 4 + i;
        float4 w0 = W4[0 * 32 + c];
        float4 w1 = W4[1 * 32 + c];
        float4 w2 = W4[2 * 32 + c];
        acc0 += xv[i].x * w0.x + xv[i].y * w0.y + xv[i].z * w0.z + xv[i].w * w0.w;
        acc1 += xv[i].x * w1.x + xv[i].y * w1.y + xv[i].z * w1.z + xv[i].w * w1.w;
        acc2 += xv[i].x * w2.x + xv[i].y * w2.y + xv[i].z * w2.z + xv[i].w * w2.w;
    }
    #pragma unroll
    for (int off = 4; off; off >>= 1) {     // reduce within 8-lane group
        acc0 += __shfl_xor_sync(FULLM, acc0, off);
        acc1 += __shfl_xor_sync(FULLM, acc1, off);
        acc2 += __shfl_xor_sync(FULLM, acc2, off);
    }

    if (r == 0) {
        const float* gr = gu + (size_t)row * 3;
        float g0 = -logf(-logf(gr[0] + EPSF) + EPSF);
        float g1 = -logf(-logf(gr[1] + EPSF) + EPSF);
        float g2 = -logf(-logf(gr[2] + EPSF) + EPSF);
        float s0 = acc0 + bias[0] + g0;
        float s1 = acc1 + bias[1] + g1;
        float s2 = acc2 + bias[2] + g2;
        int tt = 0; float best = s0;
        if (s1 > best) { best = s1; tt = 1; }   // strictly-greater = first-max wins
        if (s2 > best) { best = s2; tt = 2; }
        g_tt[row] = tt;
    }
}

// ---------------------------------------------------------------------------
// Kernel B: per-batch warp-shuffle suffix-min scan -> per-row [lo, hi].
// 2 blocks x 1024 threads, 2 elements per thread.
// ---------------------------------------------------------------------------
__global__ void __launch_bounds__(1024) k_scan() {
    int b    = blockIdx.x;
    int tid  = threadIdx.x;
    int lane = tid & 31;
    int wid  = tid >> 5;                 // 32 warps

    int i0 = 2 * tid, i1 = 2 * tid + 1;
    int t0 = g_tt[b * SS + i0];
    int t1 = g_tt[b * SS + i1];
    int a  = (t0 == 0) ? i0 : SS;        // gidx values
    int c  = (t1 == 0) ? i1 : SS;
    int p  = min(a, c);                  // per-thread pair min

    // Inclusive suffix-min scan of p within warp
    int inc = p;
    #pragma unroll
    for (int off = 1; off < 32; off <<= 1) {
        int v = __shfl_down_sync(FULLM, inc, off);
        if (lane + off < 32) inc = min(inc, v);
    }
    // Exclusive suffix (elements strictly after this thread, within warp)
    int excl = __shfl_down_sync(FULLM, inc, 1);
    if (lane == 31) excl = SS;

    __shared__ int wmin[32];
    __shared__ int wsuf[32];
    if (lane == 0) wmin[wid] = inc;      // warp's overall min
    __syncthreads();
    if (wid == 0) {
        int m = wmin[lane];
        int winc = m;
        #pragma unroll
        for (int off = 1; off < 32; off <<= 1) {
            int v = __shfl_down_sync(FULLM, winc, off);
            if (lane + off < 32) winc = min(winc, v);
        }
        int wex = __shfl_down_sync(FULLM, winc, 1);
        if (lane == 31) wex = SS;
        wsuf[lane] = wex;                // min over strictly-later warps
    }
    __syncthreads();
    int later = wsuf[wid];

    int ng1 = min(excl, later);          // next_global[i1] (elements > i1)
    int ng0 = min(c, ng1);               // next_global[i0]

    // Row i0
    {
        int lo = 0, hi = i0;
        if (t0 == 1)      { lo = i0; hi = i0; }
        else if (t0 == 2) { hi = min(i0, ng0); }
        g_lo[b * SS + i0] = lo;
        g_hi[b * SS + i0] = hi;
    }
    // Row i1
    {
        int lo = 0, hi = i1;
        if (t1 == 1)      { lo = i1; hi = i1; }
        else if (t1 == 2) { hi = min(i1, ng1); }
        g_lo[b * SS + i1] = lo;
        g_hi[b * SS + i1] = hi;
    }
}

// ---------------------------------------------------------------------------
// Kernel C: stream 268 MB of mask. One block per (b,h,s) row: 2048 floats.
// 512 threads, one float4 streaming store each (evict-first: write-once data).
// ---------------------------------------------------------------------------
__global__ void __launch_bounds__(512) k_write(float4* __restrict__ out) {
    int row = blockIdx.x;            // over B*H*S = 32768
    int s   = row & (SS - 1);
    int b   = row >> 14;             // / (H*S) = / 16384
    int lo  = g_lo[b * SS + s];
    int hi  = g_hi[b * SS + s];

    float4* orow = out + (size_t)row * (SS / 4);
    int q = threadIdx.x;
    int j = q << 2;
    float4 v;
    v.x = (j     >= lo && j     <= hi) ? 1.0f : 0.0f;
    v.y = (j + 1 >= lo && j + 1 <= hi) ? 1.0f : 0.0f;
    v.z = (j + 2 >= lo && j + 2 <= hi) ? 1.0f : 0.0f;
    v.w = (j + 3 >= lo && j + 3 <= hi) ? 1.0f : 0.0f;
    __stcs(&orow[q], v);
}

extern "C" void kernel_launch(void* const* d_in, const int* in_sizes, int n_in,
                              void* d_out, int out_size) {
    const float* x    = (const float*)d_in[0];  // input_tensor (B,S,D)
    // d_in[1] = token_types (unused by reference)
    const float* gu   = (const float*)d_in[2];  // gumbel_u (B,S,3)
    const float* W    = (const float*)d_in[3];  // (3,D)
    const float* bias = (const float*)d_in[4];  // (3,)
    float4* out = (float4*)d_out;

    k_tt<<<(BB * SS * 8) / 256, 256>>>(x, gu, W, bias);   // 128 blocks
    k_scan<<<BB, 1024>>>();
    k_write<<<BB * HH * SS, 512>>>(out);
}